// round 15
// baseline (speedup 1.0000x reference)
#include <cuda_runtime.h>
#include <math.h>

#define BATCH 2
#define NPTS 4096
#define MPTS 4096
#define NSTEPS 8
#define TOLER 1e-6f

#define TPB 128
#define MSPLIT 64
#define MCH 64                          // targets per nn tile
#define NCHB 16                         // chunks of 256 queries per batch
#define QCH 256                         // queries per chunk (2 per thread)
#define NN_BLKS (BATCH * NCHB * MSPLIT) // 2048
#define TAIL_BLKS 64                    // one per 128 points
#define NCNT (BATCH * NCHB)             // 32 producer counters
#define TOTAL_BLKS (NN_BLKS + TAIL_BLKS + 1)

// ---------------- device state ----------------
__device__ float4 g_tgt4[BATCH * MPTS];             // (x,y,z,|t|^2)
__device__ unsigned long long g_scr[BATCH * NPTS];  // packed (orderable score | idx)
__device__ float g_Rcum[BATCH][9];
__device__ float g_tcum[BATCH][3];
__device__ float g_err[BATCH];
__device__ int g_done;
__device__ unsigned g_cnt[NCNT * 32];               // per-(b,chunk) counters, 128B apart
__device__ unsigned g_tailcnt;
__device__ float g_part[TAIL_BLKS][16];

// ---------------- init ----------------
__global__ void init_kernel(const float* __restrict__ ptgt) {
    int i = blockIdx.x * blockDim.x + threadIdx.x;  // 0..8191
    if (i < BATCH * MPTS) {
        float x = ptgt[i * 3 + 0];
        float y = ptgt[i * 3 + 1];
        float z = ptgt[i * 3 + 2];
        g_tgt4[i] = make_float4(x, y, z, x * x + y * y + z * z);
        g_scr[i] = 0xFFFFFFFFFFFFFFFFull;
    }
    if (i < NCNT * 32) g_cnt[i] = 0u;
    if (i == 0) { g_done = 0; g_tailcnt = 0u; }
    if (i < BATCH) {
        g_err[i] = 0.0f;
        float* R = g_Rcum[i];
        R[0] = 1.f; R[1] = 0.f; R[2] = 0.f;
        R[3] = 0.f; R[4] = 1.f; R[5] = 0.f;
        R[6] = 0.f; R[7] = 0.f; R[8] = 1.f;
        g_tcum[i][0] = 0.f; g_tcum[i][1] = 0.f; g_tcum[i][2] = 0.f;
    }
}

// ---------------- float Horn quaternion Kabsch ----------------
__device__ __forceinline__ void matmul4(float* C, const float* A, const float* Bm) {
#pragma unroll
    for (int i = 0; i < 4; i++)
#pragma unroll
        for (int j = 0; j < 4; j++) {
            float a = 0.f;
#pragma unroll
            for (int k = 0; k < 4; k++) a = __fmaf_rn(A[i * 4 + k], Bm[k * 4 + j], a);
            C[i * 4 + j] = a;
        }
}

__device__ void solve_horn_f(const float* S, float* Rn, float* tn) {
    const float n = (float)NPTS;
    const float inv = 1.0f / n;
    const float pmx = S[0] * inv, pmy = S[1] * inv, pmz = S[2] * inv;
    const float qmx = S[3] * inv, qmy = S[4] * inv, qmz = S[5] * inv;

    const float Sxx = S[6]  - n * pmx * qmx, Sxy = S[7]  - n * pmx * qmy, Sxz = S[8]  - n * pmx * qmz;
    const float Syx = S[9]  - n * pmy * qmx, Syy = S[10] - n * pmy * qmy, Syz = S[11] - n * pmy * qmz;
    const float Szx = S[12] - n * pmz * qmx, Szy = S[13] - n * pmz * qmy, Szz = S[14] - n * pmz * qmz;

    float K[16];
    K[0]  = Sxx + Syy + Szz; K[1]  = Syz - Szy;        K[2]  = Szx - Sxz;       K[3]  = Sxy - Syx;
    K[5]  = Sxx - Syy - Szz; K[6]  = Sxy + Syx;        K[7]  = Szx + Sxz;
    K[10] = -Sxx + Syy - Szz; K[11] = Syz + Szy;
    K[15] = -Sxx - Syy + Szz;
    K[4] = K[1]; K[8] = K[2]; K[12] = K[3]; K[9] = K[6]; K[13] = K[7]; K[14] = K[11];

    float fro = 0.f;
#pragma unroll
    for (int i = 0; i < 16; i++) fro += K[i] * K[i];
    const float sc = rsqrtf(fro + 1e-30f);

    float Kf[16];
#pragma unroll
    for (int i = 0; i < 16; i++) Kf[i] = K[i] * sc;
    Kf[0] += 1.f; Kf[5] += 1.f; Kf[10] += 1.f; Kf[15] += 1.f;  // eigs in [0,2]

    float K2[16], K4[16];
    matmul4(K2, Kf, Kf);
    matmul4(K4, K2, K2);

    float v0 = 1.f, v1 = 0.02f, v2 = 0.03f, v3 = 0.04f;
#pragma unroll 4
    for (int it = 0; it < 48; it++) {
        float w0 = K4[0]  * v0 + K4[1]  * v1 + K4[2]  * v2 + K4[3]  * v3;
        float w1 = K4[4]  * v0 + K4[5]  * v1 + K4[6]  * v2 + K4[7]  * v3;
        float w2 = K4[8]  * v0 + K4[9]  * v1 + K4[10] * v2 + K4[11] * v3;
        float w3 = K4[12] * v0 + K4[13] * v1 + K4[14] * v2 + K4[15] * v3;
        if ((it & 3) == 3) {
            float r = rsqrtf(w0 * w0 + w1 * w1 + w2 * w2 + w3 * w3 + 1e-30f);
            w0 *= r; w1 *= r; w2 *= r; w3 *= r;
        }
        v0 = w0; v1 = w1; v2 = w2; v3 = w3;
    }

    const float qw = v0, qx = v1, qy = v2, qz = v3;
    const float nn = qw * qw + qx * qx + qy * qy + qz * qz;
    const float s2 = 2.0f / nn;
    Rn[0] = 1.f - s2 * (qy * qy + qz * qz); Rn[1] = s2 * (qx * qy - qw * qz); Rn[2] = s2 * (qx * qz + qw * qy);
    Rn[3] = s2 * (qx * qy + qw * qz); Rn[4] = 1.f - s2 * (qx * qx + qz * qz); Rn[5] = s2 * (qy * qz - qw * qx);
    Rn[6] = s2 * (qx * qz - qw * qy); Rn[7] = s2 * (qy * qz + qw * qx); Rn[8] = 1.f - s2 * (qx * qx + qy * qy);

    tn[0] = qmx - (Rn[0] * pmx + Rn[1] * pmy + Rn[2] * pmz);
    tn[1] = qmy - (Rn[3] * pmx + Rn[4] * pmy + Rn[5] * pmz);
    tn[2] = qmz - (Rn[6] * pmx + Rn[7] * pmy + Rn[8] * pmz);
}

// ---------------- sync helpers ----------------
__device__ __forceinline__ void arrive(unsigned* p) {
    unsigned old;
    asm volatile("atom.acq_rel.gpu.global.add.u32 %0, [%1], %2;"
                 : "=r"(old) : "l"(p), "r"(1u) : "memory");
}
__device__ __forceinline__ void wait_ge(unsigned* p, unsigned target) {
    unsigned v;
    for (;;) {
        asm volatile("ld.acquire.gpu.global.u32 %0, [%1];"
                     : "=r"(v) : "l"(p) : "memory");
        if (v >= target) break;
        __nanosleep(32);
    }
}

// ---------------- one ICP step: NN (ILP-2, full grid) -> tail -> final ----------------
__global__ __launch_bounds__(TPB, 10) void step_kernel(const float* __restrict__ psrc,
                                                       float* __restrict__ out, int step) {
    const int tid = threadIdx.x;
    const int bx = blockIdx.x;

    // =================== NN blocks (2 queries/thread, 64-target tile) ============
    if (bx < NN_BLKS) {
        __shared__ float4 sh[MCH];
        __shared__ float sRt[12];
        __shared__ int sdone;

        const int b = bx >> 10;                 // 1024 blocks per batch
        const int mtile = bx & 63;              // 64 m-tiles
        const int nchunk = (bx >> 6) & 15;      // 16 query chunks
        const int mbase = mtile * MCH;
        const int n0 = nchunk * QCH + tid;
        const int n1 = n0 + TPB;

        if (tid < 12)
            sRt[tid] = (tid < 9) ? g_Rcum[b][tid] : g_tcum[b][tid - 9];
        if (tid == 0) sdone = g_done;
        if (tid < MCH) sh[tid] = g_tgt4[b * MPTS + mbase + tid];
        __syncthreads();

        if (!sdone) {
            const float R0 = sRt[0], R1 = sRt[1], R2 = sRt[2];
            const float R3 = sRt[3], R4 = sRt[4], R5 = sRt[5];
            const float R6 = sRt[6], R7 = sRt[7], R8 = sRt[8];
            const float t0 = sRt[9], t1 = sRt[10], t2 = sRt[11];

            const float* p0 = psrc + ((size_t)b * NPTS + n0) * 3;
            const float* p1 = psrc + ((size_t)b * NPTS + n1) * 3;
            const float x0 = p0[0], y0 = p0[1], z0 = p0[2];
            const float x1 = p1[0], y1 = p1[1], z1 = p1[2];

            const float px0 = R0 * x0 + R1 * y0 + R2 * z0 + t0;
            const float py0 = R3 * x0 + R4 * y0 + R5 * z0 + t1;
            const float pz0 = R6 * x0 + R7 * y0 + R8 * z0 + t2;
            const float px1 = R0 * x1 + R1 * y1 + R2 * z1 + t0;
            const float py1 = R3 * x1 + R4 * y1 + R5 * z1 + t1;
            const float pz1 = R6 * x1 + R7 * y1 + R8 * z1 + t2;
            const float ax0 = -2.f * px0, ay0 = -2.f * py0, az0 = -2.f * pz0;
            const float ax1 = -2.f * px1, ay1 = -2.f * py1, az1 = -2.f * pz1;

            float bs0 = 3.0e38f, bs1 = 3.0e38f;
            int bi0 = 0, bi1 = 0;
#pragma unroll 8
            for (int m = 0; m < MCH; m++) {
                const float4 t = sh[m];       // warp-uniform broadcast, amortized 2x
                float s0 = __fmaf_rn(ax0, t.x, t.w);
                s0 = __fmaf_rn(ay0, t.y, s0);
                s0 = __fmaf_rn(az0, t.z, s0);
                float s1 = __fmaf_rn(ax1, t.x, t.w);
                s1 = __fmaf_rn(ay1, t.y, s1);
                s1 = __fmaf_rn(az1, t.z, s1);
                if (s0 < bs0) { bs0 = s0; bi0 = m; }
                if (s1 < bs1) { bs1 = s1; bi1 = m; }
            }

            unsigned u0 = __float_as_uint(bs0);
            u0 = (u0 & 0x80000000u) ? ~u0 : (u0 | 0x80000000u);
            unsigned u1 = __float_as_uint(bs1);
            u1 = (u1 & 0x80000000u) ? ~u1 : (u1 | 0x80000000u);
            atomicMin(g_scr + (size_t)b * NPTS + n0,
                      ((unsigned long long)u0 << 32) | (unsigned)(mbase + bi0));
            atomicMin(g_scr + (size_t)b * NPTS + n1,
                      ((unsigned long long)u1 << 32) | (unsigned)(mbase + bi1));
        }
        __syncthreads();
        if (tid == 0) arrive(&g_cnt[(b * NCHB + nchunk) * 32]);
        return;
    }

    // =================== tail blocks (one per 128 points) ===================
    if (bx < NN_BLKS + TAIL_BLKS) {
        __shared__ float sRt[12];
        __shared__ int sdone;
        __shared__ float sm[4][16];

        const int t = bx - NN_BLKS;
        const int b = t >> 5;
        const int seg = t & 31;            // 128-point segment within batch
        const int chunk = seg >> 1;        // producer chunk (256 points)

        if (tid == 0) wait_ge(&g_cnt[(b * NCHB + chunk) * 32], MSPLIT);
        if (tid < 12)
            sRt[tid] = (tid < 9) ? g_Rcum[b][tid] : g_tcum[b][tid - 9];
        if (tid == 0) sdone = g_done;
        __syncthreads();

        const int p = b * NPTS + seg * TPB + tid;
        float v[16];
#pragma unroll
        for (int k = 0; k < 16; k++) v[k] = 0.f;

        const unsigned long long key = __ldcg(&g_scr[p]);
        __stcg(&g_scr[p], 0xFFFFFFFFFFFFFFFFull);   // re-arm for next step

        if (!sdone) {
            unsigned u = (unsigned)(key >> 32);
            unsigned fb = (u & 0x80000000u) ? (u ^ 0x80000000u) : ~u;
            const float s = __uint_as_float(fb);
            const int idx = ((int)(unsigned)(key & 0xFFFFFFFFull)) & (MPTS - 1);
            const float4 q = g_tgt4[(b << 12) + idx];

            const float* ps = psrc + (size_t)p * 3;
            const float x = ps[0], y = ps[1], z = ps[2];
            const float R0 = sRt[0], R1 = sRt[1], R2 = sRt[2];
            const float R3 = sRt[3], R4 = sRt[4], R5 = sRt[5];
            const float R6 = sRt[6], R7 = sRt[7], R8 = sRt[8];
            const float px = R0 * x + R1 * y + R2 * z + sRt[9];
            const float py = R3 * x + R4 * y + R5 * z + sRt[10];
            const float pz = R6 * x + R7 * y + R8 * z + sRt[11];
            const float pn = px * px + py * py + pz * pz;
            const float dist = sqrtf(fmaxf(pn + s, 0.0f));

            v[0] = px; v[1] = py; v[2] = pz;
            v[3] = q.x; v[4] = q.y; v[5] = q.z;
            v[6] = px * q.x; v[7] = px * q.y; v[8] = px * q.z;
            v[9] = py * q.x; v[10] = py * q.y; v[11] = py * q.z;
            v[12] = pz * q.x; v[13] = pz * q.y; v[14] = pz * q.z;
            v[15] = dist;
        }

        // fixed-order deterministic block reduction (4 warps)
#pragma unroll
        for (int k = 0; k < 16; k++) {
            float a = v[k];
            a += __shfl_down_sync(0xffffffffu, a, 16);
            a += __shfl_down_sync(0xffffffffu, a, 8);
            a += __shfl_down_sync(0xffffffffu, a, 4);
            a += __shfl_down_sync(0xffffffffu, a, 2);
            a += __shfl_down_sync(0xffffffffu, a, 1);
            v[k] = a;
        }
        const int lane = tid & 31, warp = tid >> 5;
        if (lane == 0) {
#pragma unroll
            for (int k = 0; k < 16; k++) sm[warp][k] = v[k];
        }
        __syncthreads();
        if (tid < 16) {
            float a = sm[0][tid] + sm[1][tid] + sm[2][tid] + sm[3][tid];
            __stcg(&g_part[t][tid], a);
        }
        __syncthreads();
        if (tid == 0) arrive(&g_tailcnt);
        return;
    }

    // =================== final block ===================
    {
        __shared__ float cRt[BATCH][12];
        __shared__ float c_S[BATCH][16];
        __shared__ float c_errnew[BATCH];
        __shared__ int c_done, c_done0;

        if (tid == 0) { wait_ge(&g_tailcnt, TAIL_BLKS); c_done0 = g_done; }
        __syncthreads();
        const int done0 = c_done0;

        if (tid < 24) {
            int bb = tid / 12, j = tid - bb * 12;
            cRt[bb][j] = (j < 9) ? g_Rcum[bb][j] : g_tcum[bb][j - 9];
        }
        __syncthreads();

        if (tid < 32) {
            const int bsel = tid >> 4, k = tid & 15;
            float a = 0.f;
#pragma unroll
            for (int c = 0; c < 32; c++)               // fixed order: deterministic
                a += __ldcg(&g_part[bsel * 32 + c][k]);
            c_S[bsel][k] = a;
            if (k == 15) c_errnew[bsel] = a / (float)NPTS;
        }
        __syncthreads();

        if (tid == 0) {
            int conv = (fabsf(c_errnew[0] - g_err[0]) < TOLER) &&
                       (fabsf(c_errnew[1] - g_err[1]) < TOLER);
            c_done = (done0 || conv) ? 1 : 0;
            __stcg(&g_done, c_done);
        }
        __syncthreads();

        if (tid < BATCH && !c_done) {
            float S[16];
#pragma unroll
            for (int k = 0; k < 16; k++) S[k] = c_S[tid][k];
            float Rn[9], tn[3];
            solve_horn_f(S, Rn, tn);

            float Ro[9], to[3];
#pragma unroll
            for (int i = 0; i < 9; i++) Ro[i] = cRt[tid][i];
#pragma unroll
            for (int i = 0; i < 3; i++) to[i] = cRt[tid][9 + i];

#pragma unroll
            for (int i = 0; i < 3; i++) {
#pragma unroll
                for (int j = 0; j < 3; j++) {
                    float m = Rn[i * 3 + 0] * Ro[0 + j] + Rn[i * 3 + 1] * Ro[3 + j] +
                              Rn[i * 3 + 2] * Ro[6 + j];
                    __stcg(&g_Rcum[tid][i * 3 + j], m);
                }
                float tm = Rn[i * 3 + 0] * to[0] + Rn[i * 3 + 1] * to[1] +
                           Rn[i * 3 + 2] * to[2] + tn[i];
                __stcg(&g_tcum[tid][i], tm);
            }
            __stcg(&g_err[tid], c_errnew[tid]);
        }
        __syncthreads();

        // reset counters for next step kernel
        for (int i = tid; i < NCNT * 32; i += TPB) __stcg(&g_cnt[i], 0u);
        if (tid == 0) __stcg(&g_tailcnt, 0u);

        if (step == NSTEPS - 1 && tid < BATCH) {
            float R[9];
#pragma unroll
            for (int i = 0; i < 9; i++) R[i] = __ldcg(&g_Rcum[tid][i]);
            out[tid * 7 + 0] = __ldcg(&g_tcum[tid][0]);
            out[tid * 7 + 1] = __ldcg(&g_tcum[tid][1]);
            out[tid * 7 + 2] = __ldcg(&g_tcum[tid][2]);
            const float r00 = R[0], r11 = R[4], r22 = R[8];
            float qw = 0.5f * sqrtf(fmaxf(1.f + r00 + r11 + r22, 1e-12f));
            float qx = 0.5f * sqrtf(fmaxf(1.f + r00 - r11 - r22, 1e-12f));
            float qy = 0.5f * sqrtf(fmaxf(1.f - r00 + r11 - r22, 1e-12f));
            float qz = 0.5f * sqrtf(fmaxf(1.f - r00 - r11 + r22, 1e-12f));
            qx = (R[7] - R[5] >= 0.f) ? qx : -qx;
            qy = (R[2] - R[6] >= 0.f) ? qy : -qy;
            qz = (R[3] - R[1] >= 0.f) ? qz : -qz;
            out[tid * 7 + 3] = qx;
            out[tid * 7 + 4] = qy;
            out[tid * 7 + 5] = qz;
            out[tid * 7 + 6] = qw;
        }
    }
}

// ---------------- launch ----------------
extern "C" void kernel_launch(void* const* d_in, const int* in_sizes, int n_in,
                              void* d_out, int out_size) {
    const float* psrc = (const float*)d_in[0];
    const float* ptgt = (const float*)d_in[1];
    float* out = (float*)d_out;

    init_kernel<<<(BATCH * MPTS + 255) / 256, 256>>>(ptgt);
    for (int s = 0; s < NSTEPS; s++)
        step_kernel<<<TOTAL_BLKS, TPB>>>(psrc, out, s);
}

// round 16
// speedup vs baseline: 1.1136x; 1.1136x over previous
#include <cuda_runtime.h>
#include <math.h>

#define BATCH 2
#define NPTS 4096
#define MPTS 4096
#define NSTEPS 8
#define TOLER 1e-6f

#define TPB 128
#define MSPLIT 32
#define MCH 128                         // targets per nn tile (== TPB)
#define NCHB 32                         // n-chunks per batch (128 pts each)
#define NN_BLKS (BATCH * NCHB * MSPLIT) // 2048 per step
#define TAIL_BLKS (BATCH * NCHB)        // 64 per step
#define PER_STEP (NN_BLKS + TAIL_BLKS + 1)   // 2113
#define TOTAL_BLKS (PER_STEP * NSTEPS)
#define NCNT (BATCH * NCHB)             // 64 producer counters per step

// ---------------- device state ----------------
__device__ float4 g_tgt4[BATCH * MPTS];             // (x,y,z,|t|^2)
__device__ unsigned long long g_scr[BATCH * NPTS];  // packed (orderable score | idx)
__device__ float g_Rcum[BATCH][9];
__device__ float g_tcum[BATCH][3];
__device__ float g_err[BATCH];
__device__ int g_done;
__device__ unsigned g_cnt[NSTEPS][NCNT * 32];       // per-step per-chunk counters, 128B apart
__device__ unsigned g_tailcnt[NSTEPS * 32];         // per-step tail counters, 128B apart
__device__ unsigned g_phase;                        // completed-steps counter
__device__ float g_part[NSTEPS][TAIL_BLKS][16];

// ---------------- init ----------------
__global__ void init_kernel(const float* __restrict__ ptgt) {
    int i = blockIdx.x * blockDim.x + threadIdx.x;  // 0..8191
    if (i < BATCH * MPTS) {
        float x = ptgt[i * 3 + 0];
        float y = ptgt[i * 3 + 1];
        float z = ptgt[i * 3 + 2];
        g_tgt4[i] = make_float4(x, y, z, x * x + y * y + z * z);
        g_scr[i] = 0xFFFFFFFFFFFFFFFFull;
    }
    for (int j = i; j < NSTEPS * NCNT * 32; j += 8192)
        g_cnt[j / (NCNT * 32)][j % (NCNT * 32)] = 0u;
    if (i < NSTEPS * 32) g_tailcnt[i] = 0u;
    if (i == 0) { g_done = 0; g_phase = 0u; }
    if (i < BATCH) {
        g_err[i] = 0.0f;
        float* R = g_Rcum[i];
        R[0] = 1.f; R[1] = 0.f; R[2] = 0.f;
        R[3] = 0.f; R[4] = 1.f; R[5] = 0.f;
        R[6] = 0.f; R[7] = 0.f; R[8] = 1.f;
        g_tcum[i][0] = 0.f; g_tcum[i][1] = 0.f; g_tcum[i][2] = 0.f;
    }
}

// ---------------- float Horn quaternion Kabsch ----------------
__device__ __forceinline__ void matmul4(float* C, const float* A, const float* Bm) {
#pragma unroll
    for (int i = 0; i < 4; i++)
#pragma unroll
        for (int j = 0; j < 4; j++) {
            float a = 0.f;
#pragma unroll
            for (int k = 0; k < 4; k++) a = __fmaf_rn(A[i * 4 + k], Bm[k * 4 + j], a);
            C[i * 4 + j] = a;
        }
}

__device__ void solve_horn_f(const float* S, float* Rn, float* tn) {
    const float n = (float)NPTS;
    const float inv = 1.0f / n;
    const float pmx = S[0] * inv, pmy = S[1] * inv, pmz = S[2] * inv;
    const float qmx = S[3] * inv, qmy = S[4] * inv, qmz = S[5] * inv;

    const float Sxx = S[6]  - n * pmx * qmx, Sxy = S[7]  - n * pmx * qmy, Sxz = S[8]  - n * pmx * qmz;
    const float Syx = S[9]  - n * pmy * qmx, Syy = S[10] - n * pmy * qmy, Syz = S[11] - n * pmy * qmz;
    const float Szx = S[12] - n * pmz * qmx, Szy = S[13] - n * pmz * qmy, Szz = S[14] - n * pmz * qmz;

    float K[16];
    K[0]  = Sxx + Syy + Szz; K[1]  = Syz - Szy;        K[2]  = Szx - Sxz;       K[3]  = Sxy - Syx;
    K[5]  = Sxx - Syy - Szz; K[6]  = Sxy + Syx;        K[7]  = Szx + Sxz;
    K[10] = -Sxx + Syy - Szz; K[11] = Syz + Szy;
    K[15] = -Sxx - Syy + Szz;
    K[4] = K[1]; K[8] = K[2]; K[12] = K[3]; K[9] = K[6]; K[13] = K[7]; K[14] = K[11];

    float fro = 0.f;
#pragma unroll
    for (int i = 0; i < 16; i++) fro += K[i] * K[i];
    const float sc = rsqrtf(fro + 1e-30f);

    float Kf[16];
#pragma unroll
    for (int i = 0; i < 16; i++) Kf[i] = K[i] * sc;
    Kf[0] += 1.f; Kf[5] += 1.f; Kf[10] += 1.f; Kf[15] += 1.f;  // eigs in [0,2]

    float K2[16], K4[16];
    matmul4(K2, Kf, Kf);
    matmul4(K4, K2, K2);

    float v0 = 1.f, v1 = 0.02f, v2 = 0.03f, v3 = 0.04f;
#pragma unroll 4
    for (int it = 0; it < 48; it++) {
        float w0 = K4[0]  * v0 + K4[1]  * v1 + K4[2]  * v2 + K4[3]  * v3;
        float w1 = K4[4]  * v0 + K4[5]  * v1 + K4[6]  * v2 + K4[7]  * v3;
        float w2 = K4[8]  * v0 + K4[9]  * v1 + K4[10] * v2 + K4[11] * v3;
        float w3 = K4[12] * v0 + K4[13] * v1 + K4[14] * v2 + K4[15] * v3;
        if ((it & 3) == 3) {
            float r = rsqrtf(w0 * w0 + w1 * w1 + w2 * w2 + w3 * w3 + 1e-30f);
            w0 *= r; w1 *= r; w2 *= r; w3 *= r;
        }
        v0 = w0; v1 = w1; v2 = w2; v3 = w3;
    }

    const float qw = v0, qx = v1, qy = v2, qz = v3;
    const float nn = qw * qw + qx * qx + qy * qy + qz * qz;
    const float s2 = 2.0f / nn;
    Rn[0] = 1.f - s2 * (qy * qy + qz * qz); Rn[1] = s2 * (qx * qy - qw * qz); Rn[2] = s2 * (qx * qz + qw * qy);
    Rn[3] = s2 * (qx * qy + qw * qz); Rn[4] = 1.f - s2 * (qx * qx + qz * qz); Rn[5] = s2 * (qy * qz - qw * qx);
    Rn[6] = s2 * (qx * qz - qw * qy); Rn[7] = s2 * (qy * qz + qw * qx); Rn[8] = 1.f - s2 * (qx * qx + qy * qy);

    tn[0] = qmx - (Rn[0] * pmx + Rn[1] * pmy + Rn[2] * pmz);
    tn[1] = qmy - (Rn[3] * pmx + Rn[4] * pmy + Rn[5] * pmz);
    tn[2] = qmz - (Rn[6] * pmx + Rn[7] * pmy + Rn[8] * pmz);
}

// ---------------- sync helpers ----------------
__device__ __forceinline__ void arrive(unsigned* p) {
    unsigned old;
    asm volatile("atom.acq_rel.gpu.global.add.u32 %0, [%1], %2;"
                 : "=r"(old) : "l"(p), "r"(1u) : "memory");
}
__device__ __forceinline__ void wait_ge(unsigned* p, unsigned target) {
    unsigned v;
    for (;;) {
        asm volatile("ld.acquire.gpu.global.u32 %0, [%1];"
                     : "=r"(v) : "l"(p) : "memory");
        if (v >= target) break;
        __nanosleep(32);
    }
}
__device__ __forceinline__ void release_phase(unsigned* p, unsigned val) {
    asm volatile("st.release.gpu.global.u32 [%0], %1;" :: "l"(p), "r"(val) : "memory");
}

// ---------------- all 8 ICP steps in ONE launch (cross-step dataflow) ----------------
__global__ __launch_bounds__(TPB, 10) void icp_all_kernel(const float* __restrict__ psrc,
                                                          float* __restrict__ out) {
    const int tid = threadIdx.x;
    const int step = blockIdx.x / PER_STEP;
    const int bx = blockIdx.x - step * PER_STEP;

    // =================== NN blocks ===================
    if (bx < NN_BLKS) {
        __shared__ float4 sh[MCH];
        __shared__ float sRt[12];
        __shared__ int sdone;

        const int b = bx >> 10;
        const int mtile = bx & 31;
        const int nchunk = (bx >> 5) & 31;
        const int mbase = mtile * MCH;
        const int n = nchunk * TPB + tid;

        // wait for previous step's solve to publish R/t/done
        if (tid == 0 && step > 0) wait_ge(&g_phase, (unsigned)step);
        __syncthreads();

        if (tid < 12)
            sRt[tid] = (tid < 9) ? __ldcg(&g_Rcum[b][tid]) : __ldcg(&g_tcum[b][tid - 9]);
        if (tid == 0) sdone = __ldcg(&g_done);
        sh[tid] = g_tgt4[b * MPTS + mbase + tid];
        __syncthreads();

        if (!sdone) {
            const float R0 = sRt[0], R1 = sRt[1], R2 = sRt[2];
            const float R3 = sRt[3], R4 = sRt[4], R5 = sRt[5];
            const float R6 = sRt[6], R7 = sRt[7], R8 = sRt[8];
            const float t0 = sRt[9], t1 = sRt[10], t2 = sRt[11];

            const float* ps = psrc + ((size_t)b * NPTS + n) * 3;
            const float x = ps[0], y = ps[1], z = ps[2];
            const float px = R0 * x + R1 * y + R2 * z + t0;
            const float py = R3 * x + R4 * y + R5 * z + t1;
            const float pz = R6 * x + R7 * y + R8 * z + t2;
            const float ax = -2.0f * px, ay = -2.0f * py, az = -2.0f * pz;

            float bs = 3.0e38f;
            int bi = 0;
#pragma unroll 8
            for (int m = 0; m < MCH; m++) {
                const float4 t = sh[m];       // warp-uniform broadcast
                float s = __fmaf_rn(ax, t.x, t.w);
                s = __fmaf_rn(ay, t.y, s);
                s = __fmaf_rn(az, t.z, s);
                if (s < bs) { bs = s; bi = m; }
            }

            unsigned u = __float_as_uint(bs);
            u = (u & 0x80000000u) ? ~u : (u | 0x80000000u);
            atomicMin(g_scr + (size_t)b * NPTS + n,
                      ((unsigned long long)u << 32) | (unsigned)(mbase + bi));
        }
        __syncthreads();
        if (tid == 0) arrive(&g_cnt[step][(b * NCHB + nchunk) * 32]);
        return;
    }

    // =================== tail blocks ===================
    if (bx < NN_BLKS + TAIL_BLKS) {
        __shared__ float sRt[12];
        __shared__ int sdone;
        __shared__ float sm[4][16];

        const int t = bx - NN_BLKS;
        const int b = t >> 5;
        const int nchunk = t & 31;

        // waiting on this step's producers transitively orders us after phase>=step
        if (tid == 0) wait_ge(&g_cnt[step][t * 32], MSPLIT);
        __syncthreads();
        if (tid < 12)
            sRt[tid] = (tid < 9) ? __ldcg(&g_Rcum[b][tid]) : __ldcg(&g_tcum[b][tid - 9]);
        if (tid == 0) sdone = __ldcg(&g_done);
        __syncthreads();

        const int p = b * NPTS + nchunk * TPB + tid;
        float v[16];
#pragma unroll
        for (int k = 0; k < 16; k++) v[k] = 0.f;

        const unsigned long long key = __ldcg(&g_scr[p]);
        __stcg(&g_scr[p], 0xFFFFFFFFFFFFFFFFull);   // re-arm for next step

        if (!sdone) {
            unsigned u = (unsigned)(key >> 32);
            unsigned fb = (u & 0x80000000u) ? (u ^ 0x80000000u) : ~u;
            const float s = __uint_as_float(fb);
            const int idx = ((int)(unsigned)(key & 0xFFFFFFFFull)) & (MPTS - 1);
            const float4 q = g_tgt4[(b << 12) + idx];

            const float* ps = psrc + (size_t)p * 3;
            const float x = ps[0], y = ps[1], z = ps[2];
            const float R0 = sRt[0], R1 = sRt[1], R2 = sRt[2];
            const float R3 = sRt[3], R4 = sRt[4], R5 = sRt[5];
            const float R6 = sRt[6], R7 = sRt[7], R8 = sRt[8];
            const float px = R0 * x + R1 * y + R2 * z + sRt[9];
            const float py = R3 * x + R4 * y + R5 * z + sRt[10];
            const float pz = R6 * x + R7 * y + R8 * z + sRt[11];
            const float pn = px * px + py * py + pz * pz;
            const float dist = sqrtf(fmaxf(pn + s, 0.0f));

            v[0] = px; v[1] = py; v[2] = pz;
            v[3] = q.x; v[4] = q.y; v[5] = q.z;
            v[6] = px * q.x; v[7] = px * q.y; v[8] = px * q.z;
            v[9] = py * q.x; v[10] = py * q.y; v[11] = py * q.z;
            v[12] = pz * q.x; v[13] = pz * q.y; v[14] = pz * q.z;
            v[15] = dist;
        }

        // fixed-order deterministic block reduction (4 warps)
#pragma unroll
        for (int k = 0; k < 16; k++) {
            float a = v[k];
            a += __shfl_down_sync(0xffffffffu, a, 16);
            a += __shfl_down_sync(0xffffffffu, a, 8);
            a += __shfl_down_sync(0xffffffffu, a, 4);
            a += __shfl_down_sync(0xffffffffu, a, 2);
            a += __shfl_down_sync(0xffffffffu, a, 1);
            v[k] = a;
        }
        const int lane = tid & 31, warp = tid >> 5;
        if (lane == 0) {
#pragma unroll
            for (int k = 0; k < 16; k++) sm[warp][k] = v[k];
        }
        __syncthreads();
        if (tid < 16) {
            float a = sm[0][tid] + sm[1][tid] + sm[2][tid] + sm[3][tid];
            __stcg(&g_part[step][t][tid], a);
        }
        __syncthreads();
        if (tid == 0) arrive(&g_tailcnt[step * 32]);
        return;
    }

    // =================== final block ===================
    {
        __shared__ float cRt[BATCH][12];
        __shared__ float c_S[BATCH][16];
        __shared__ float c_errnew[BATCH];
        __shared__ int c_done, c_done0;

        if (tid == 0) { wait_ge(&g_tailcnt[step * 32], TAIL_BLKS); c_done0 = __ldcg(&g_done); }
        __syncthreads();
        const int done0 = c_done0;

        if (tid < 24) {
            int bb = tid / 12, j = tid - bb * 12;
            cRt[bb][j] = (j < 9) ? __ldcg(&g_Rcum[bb][j]) : __ldcg(&g_tcum[bb][j - 9]);
        }
        __syncthreads();

        if (tid < 32) {
            const int bsel = tid >> 4, k = tid & 15;
            float a = 0.f;
#pragma unroll
            for (int c = 0; c < NCHB; c++)             // fixed order: deterministic
                a += __ldcg(&g_part[step][bsel * NCHB + c][k]);
            c_S[bsel][k] = a;
            if (k == 15) c_errnew[bsel] = a / (float)NPTS;
        }
        __syncthreads();

        if (tid == 0) {
            int conv = (fabsf(c_errnew[0] - __ldcg(&g_err[0])) < TOLER) &&
                       (fabsf(c_errnew[1] - __ldcg(&g_err[1])) < TOLER);
            c_done = (done0 || conv) ? 1 : 0;
            __stcg(&g_done, c_done);
        }
        __syncthreads();

        if (tid < BATCH && !c_done) {
            float S[16];
#pragma unroll
            for (int k = 0; k < 16; k++) S[k] = c_S[tid][k];
            float Rn[9], tn[3];
            solve_horn_f(S, Rn, tn);

            float Ro[9], to[3];
#pragma unroll
            for (int i = 0; i < 9; i++) Ro[i] = cRt[tid][i];
#pragma unroll
            for (int i = 0; i < 3; i++) to[i] = cRt[tid][9 + i];

#pragma unroll
            for (int i = 0; i < 3; i++) {
#pragma unroll
                for (int j = 0; j < 3; j++) {
                    float m = Rn[i * 3 + 0] * Ro[0 + j] + Rn[i * 3 + 1] * Ro[3 + j] +
                              Rn[i * 3 + 2] * Ro[6 + j];
                    __stcg(&g_Rcum[tid][i * 3 + j], m);
                }
                float tm = Rn[i * 3 + 0] * to[0] + Rn[i * 3 + 1] * to[1] +
                           Rn[i * 3 + 2] * to[2] + tn[i];
                __stcg(&g_tcum[tid][i], tm);
            }
            __stcg(&g_err[tid], c_errnew[tid]);
        }
        __syncthreads();

        if (step == NSTEPS - 1) {
            if (tid < BATCH) {
                float R[9];
#pragma unroll
                for (int i = 0; i < 9; i++) R[i] = __ldcg(&g_Rcum[tid][i]);
                out[tid * 7 + 0] = __ldcg(&g_tcum[tid][0]);
                out[tid * 7 + 1] = __ldcg(&g_tcum[tid][1]);
                out[tid * 7 + 2] = __ldcg(&g_tcum[tid][2]);
                const float r00 = R[0], r11 = R[4], r22 = R[8];
                float qw = 0.5f * sqrtf(fmaxf(1.f + r00 + r11 + r22, 1e-12f));
                float qx = 0.5f * sqrtf(fmaxf(1.f + r00 - r11 - r22, 1e-12f));
                float qy = 0.5f * sqrtf(fmaxf(1.f - r00 + r11 - r22, 1e-12f));
                float qz = 0.5f * sqrtf(fmaxf(1.f - r00 - r11 + r22, 1e-12f));
                qx = (R[7] - R[5] >= 0.f) ? qx : -qx;
                qy = (R[2] - R[6] >= 0.f) ? qy : -qy;
                qz = (R[3] - R[1] >= 0.f) ? qz : -qz;
                out[tid * 7 + 3] = qx;
                out[tid * 7 + 4] = qy;
                out[tid * 7 + 5] = qz;
                out[tid * 7 + 6] = qw;
            }
        } else {
            if (tid == 0) release_phase(&g_phase, (unsigned)(step + 1));
        }
    }
}

// ---------------- launch ----------------
extern "C" void kernel_launch(void* const* d_in, const int* in_sizes, int n_in,
                              void* d_out, int out_size) {
    const float* psrc = (const float*)d_in[0];
    const float* ptgt = (const float*)d_in[1];
    float* out = (float*)d_out;

    init_kernel<<<(BATCH * MPTS + 255) / 256, 256>>>(ptgt);
    icp_all_kernel<<<TOTAL_BLKS, TPB>>>(psrc, out);
}

// round 17
// speedup vs baseline: 1.1333x; 1.0177x over previous
#include <cuda_runtime.h>
#include <math.h>

#define BATCH 2
#define NPTS 4096
#define MPTS 4096
#define NSTEPS 8
#define TOLER 1e-6f

#define TPB 128
#define MSPLIT 32
#define MCH 128                         // targets per nn tile (== TPB)
#define NCHB 32                         // n-chunks per batch (128 pts each)
#define NN_BLKS (BATCH * NCHB * MSPLIT) // 2048 per step
#define PER_STEP (NN_BLKS + 1)          // 2049 (tails inlined into last NN arriver)
#define TOTAL_BLKS (PER_STEP * NSTEPS)
#define NCNT (BATCH * NCHB)             // 64 chunk counters per step

// ---------------- device state ----------------
__device__ float4 g_tgt4[BATCH * MPTS];             // (x,y,z,|t|^2)
__device__ unsigned long long g_scr[BATCH * NPTS];  // packed (orderable score | idx)
__device__ float g_Rcum[BATCH][9];
__device__ float g_tcum[BATCH][3];
__device__ float g_err[BATCH];
__device__ int g_done;
__device__ unsigned g_cnt[NSTEPS][NCNT * 32];       // per-step per-chunk counters, 128B apart
__device__ unsigned g_tailcnt[NSTEPS * 32];         // per-step tail counters, 128B apart
__device__ unsigned g_phase;                        // completed-steps counter
__device__ float g_part[NSTEPS][NCNT][16];

// ---------------- init ----------------
__global__ void init_kernel(const float* __restrict__ ptgt) {
    int i = blockIdx.x * blockDim.x + threadIdx.x;  // 0..8191
    if (i < BATCH * MPTS) {
        float x = ptgt[i * 3 + 0];
        float y = ptgt[i * 3 + 1];
        float z = ptgt[i * 3 + 2];
        g_tgt4[i] = make_float4(x, y, z, x * x + y * y + z * z);
        g_scr[i] = 0xFFFFFFFFFFFFFFFFull;
    }
    for (int j = i; j < NSTEPS * NCNT * 32; j += 8192)
        g_cnt[j / (NCNT * 32)][j % (NCNT * 32)] = 0u;
    if (i < NSTEPS * 32) g_tailcnt[i] = 0u;
    if (i == 0) { g_done = 0; g_phase = 0u; }
    if (i < BATCH) {
        g_err[i] = 0.0f;
        float* R = g_Rcum[i];
        R[0] = 1.f; R[1] = 0.f; R[2] = 0.f;
        R[3] = 0.f; R[4] = 1.f; R[5] = 0.f;
        R[6] = 0.f; R[7] = 0.f; R[8] = 1.f;
        g_tcum[i][0] = 0.f; g_tcum[i][1] = 0.f; g_tcum[i][2] = 0.f;
    }
}

// ---------------- float Horn quaternion Kabsch ----------------
__device__ __forceinline__ void matmul4(float* C, const float* A, const float* Bm) {
#pragma unroll
    for (int i = 0; i < 4; i++)
#pragma unroll
        for (int j = 0; j < 4; j++) {
            float a = 0.f;
#pragma unroll
            for (int k = 0; k < 4; k++) a = __fmaf_rn(A[i * 4 + k], Bm[k * 4 + j], a);
            C[i * 4 + j] = a;
        }
}

__device__ void solve_horn_f(const float* S, float* Rn, float* tn) {
    const float n = (float)NPTS;
    const float inv = 1.0f / n;
    const float pmx = S[0] * inv, pmy = S[1] * inv, pmz = S[2] * inv;
    const float qmx = S[3] * inv, qmy = S[4] * inv, qmz = S[5] * inv;

    const float Sxx = S[6]  - n * pmx * qmx, Sxy = S[7]  - n * pmx * qmy, Sxz = S[8]  - n * pmx * qmz;
    const float Syx = S[9]  - n * pmy * qmx, Syy = S[10] - n * pmy * qmy, Syz = S[11] - n * pmy * qmz;
    const float Szx = S[12] - n * pmz * qmx, Szy = S[13] - n * pmz * qmy, Szz = S[14] - n * pmz * qmz;

    float K[16];
    K[0]  = Sxx + Syy + Szz; K[1]  = Syz - Szy;        K[2]  = Szx - Sxz;       K[3]  = Sxy - Syx;
    K[5]  = Sxx - Syy - Szz; K[6]  = Sxy + Syx;        K[7]  = Szx + Sxz;
    K[10] = -Sxx + Syy - Szz; K[11] = Syz + Szy;
    K[15] = -Sxx - Syy + Szz;
    K[4] = K[1]; K[8] = K[2]; K[12] = K[3]; K[9] = K[6]; K[13] = K[7]; K[14] = K[11];

    float fro = 0.f;
#pragma unroll
    for (int i = 0; i < 16; i++) fro += K[i] * K[i];
    const float sc = rsqrtf(fro + 1e-30f);

    float Kf[16];
#pragma unroll
    for (int i = 0; i < 16; i++) Kf[i] = K[i] * sc;
    Kf[0] += 1.f; Kf[5] += 1.f; Kf[10] += 1.f; Kf[15] += 1.f;  // eigs in [0,2]

    float K2[16], K4[16];
    matmul4(K2, Kf, Kf);
    matmul4(K4, K2, K2);

    float v0 = 1.f, v1 = 0.02f, v2 = 0.03f, v3 = 0.04f;
#pragma unroll 4
    for (int it = 0; it < 48; it++) {
        float w0 = K4[0]  * v0 + K4[1]  * v1 + K4[2]  * v2 + K4[3]  * v3;
        float w1 = K4[4]  * v0 + K4[5]  * v1 + K4[6]  * v2 + K4[7]  * v3;
        float w2 = K4[8]  * v0 + K4[9]  * v1 + K4[10] * v2 + K4[11] * v3;
        float w3 = K4[12] * v0 + K4[13] * v1 + K4[14] * v2 + K4[15] * v3;
        if ((it & 3) == 3) {
            float r = rsqrtf(w0 * w0 + w1 * w1 + w2 * w2 + w3 * w3 + 1e-30f);
            w0 *= r; w1 *= r; w2 *= r; w3 *= r;
        }
        v0 = w0; v1 = w1; v2 = w2; v3 = w3;
    }

    const float qw = v0, qx = v1, qy = v2, qz = v3;
    const float nn = qw * qw + qx * qx + qy * qy + qz * qz;
    const float s2 = 2.0f / nn;
    Rn[0] = 1.f - s2 * (qy * qy + qz * qz); Rn[1] = s2 * (qx * qy - qw * qz); Rn[2] = s2 * (qx * qz + qw * qy);
    Rn[3] = s2 * (qx * qy + qw * qz); Rn[4] = 1.f - s2 * (qx * qx + qz * qz); Rn[5] = s2 * (qy * qz - qw * qx);
    Rn[6] = s2 * (qx * qz - qw * qy); Rn[7] = s2 * (qy * qz + qw * qx); Rn[8] = 1.f - s2 * (qx * qx + qy * qy);

    tn[0] = qmx - (Rn[0] * pmx + Rn[1] * pmy + Rn[2] * pmz);
    tn[1] = qmy - (Rn[3] * pmx + Rn[4] * pmy + Rn[5] * pmz);
    tn[2] = qmz - (Rn[6] * pmx + Rn[7] * pmy + Rn[8] * pmz);
}

// ---------------- sync helpers ----------------
__device__ __forceinline__ unsigned arrive(unsigned* p) {
    unsigned old;
    asm volatile("atom.acq_rel.gpu.global.add.u32 %0, [%1], %2;"
                 : "=r"(old) : "l"(p), "r"(1u) : "memory");
    return old;
}
__device__ __forceinline__ void wait_ge(unsigned* p, unsigned target) {
    unsigned v;
    for (;;) {
        asm volatile("ld.acquire.gpu.global.u32 %0, [%1];"
                     : "=r"(v) : "l"(p) : "memory");
        if (v >= target) break;
        __nanosleep(32);
    }
}
__device__ __forceinline__ void release_phase(unsigned* p, unsigned val) {
    asm volatile("st.release.gpu.global.u32 [%0], %1;" :: "l"(p), "r"(val) : "memory");
}

// ---------------- all 8 ICP steps in ONE launch ----------------
__global__ __launch_bounds__(TPB, 10) void icp_all_kernel(const float* __restrict__ psrc,
                                                          float* __restrict__ out) {
    const int tid = threadIdx.x;
    const int step = blockIdx.x / PER_STEP;
    const int bx = blockIdx.x - step * PER_STEP;

    // =================== NN blocks (+ inlined tail on last arriver) ============
    if (bx < NN_BLKS) {
        __shared__ float4 sh[MCH];
        __shared__ float sRt[12];
        __shared__ int sdone;
        __shared__ int s_last;
        __shared__ float sm[4][16];

        const int b = bx >> 10;
        const int mtile = bx & 31;
        const int nchunk = (bx >> 5) & 31;
        const int mbase = mtile * MCH;
        const int n = nchunk * TPB + tid;
        const int chunk_id = b * NCHB + nchunk;

        // wait for previous step's solve to publish R/t/done
        if (tid == 0 && step > 0) wait_ge(&g_phase, (unsigned)step);
        __syncthreads();

        if (tid < 12)
            sRt[tid] = (tid < 9) ? __ldcg(&g_Rcum[b][tid]) : __ldcg(&g_tcum[b][tid - 9]);
        if (tid == 0) sdone = __ldcg(&g_done);
        sh[tid] = g_tgt4[b * MPTS + mbase + tid];
        __syncthreads();
        const int done0 = sdone;

        if (!done0) {
            const float R0 = sRt[0], R1 = sRt[1], R2 = sRt[2];
            const float R3 = sRt[3], R4 = sRt[4], R5 = sRt[5];
            const float R6 = sRt[6], R7 = sRt[7], R8 = sRt[8];
            const float t0 = sRt[9], t1 = sRt[10], t2 = sRt[11];

            const float* ps = psrc + ((size_t)b * NPTS + n) * 3;
            const float x = ps[0], y = ps[1], z = ps[2];
            const float px = R0 * x + R1 * y + R2 * z + t0;
            const float py = R3 * x + R4 * y + R5 * z + t1;
            const float pz = R6 * x + R7 * y + R8 * z + t2;
            const float ax = -2.0f * px, ay = -2.0f * py, az = -2.0f * pz;

            // two independent min chains (even/odd) -> shorter carried dependency
            float bs0 = 3.0e38f, bs1 = 3.0e38f;
            int bi0 = 0, bi1 = 1;
#pragma unroll 8
            for (int m = 0; m < MCH; m += 2) {
                const float4 te = sh[m];
                const float4 to = sh[m + 1];
                float s0 = __fmaf_rn(ax, te.x, te.w);
                s0 = __fmaf_rn(ay, te.y, s0);
                s0 = __fmaf_rn(az, te.z, s0);
                float s1 = __fmaf_rn(ax, to.x, to.w);
                s1 = __fmaf_rn(ay, to.y, s1);
                s1 = __fmaf_rn(az, to.z, s1);
                if (s0 < bs0) { bs0 = s0; bi0 = m; }
                if (s1 < bs1) { bs1 = s1; bi1 = m + 1; }
            }

            // exact merge via packed keys (tie -> smaller index)
            unsigned u0 = __float_as_uint(bs0);
            u0 = (u0 & 0x80000000u) ? ~u0 : (u0 | 0x80000000u);
            unsigned u1 = __float_as_uint(bs1);
            u1 = (u1 & 0x80000000u) ? ~u1 : (u1 | 0x80000000u);
            unsigned long long k0 = ((unsigned long long)u0 << 32) | (unsigned)(mbase + bi0);
            unsigned long long k1 = ((unsigned long long)u1 << 32) | (unsigned)(mbase + bi1);
            atomicMin(g_scr + (size_t)b * NPTS + n, k0 < k1 ? k0 : k1);
        }
        __syncthreads();

        if (tid == 0) {
            unsigned old = arrive(&g_cnt[step][chunk_id * 32]);
            s_last = (old == MSPLIT - 1) ? 1 : 0;
        }
        __syncthreads();
        if (!s_last) return;

        // ---- inlined tail: reduce this chunk's 128 points ----
        const int p = b * NPTS + nchunk * TPB + tid;
        float v[16];
#pragma unroll
        for (int k = 0; k < 16; k++) v[k] = 0.f;

        const unsigned long long key = __ldcg(&g_scr[p]);
        __stcg(&g_scr[p], 0xFFFFFFFFFFFFFFFFull);   // re-arm for next step

        if (!done0) {
            unsigned u = (unsigned)(key >> 32);
            unsigned fb = (u & 0x80000000u) ? (u ^ 0x80000000u) : ~u;
            const float s = __uint_as_float(fb);
            const int idx = ((int)(unsigned)(key & 0xFFFFFFFFull)) & (MPTS - 1);
            const float4 q = g_tgt4[(b << 12) + idx];

            const float* ps = psrc + (size_t)p * 3;
            const float x = ps[0], y = ps[1], z = ps[2];
            const float R0 = sRt[0], R1 = sRt[1], R2 = sRt[2];
            const float R3 = sRt[3], R4 = sRt[4], R5 = sRt[5];
            const float R6 = sRt[6], R7 = sRt[7], R8 = sRt[8];
            const float px = R0 * x + R1 * y + R2 * z + sRt[9];
            const float py = R3 * x + R4 * y + R5 * z + sRt[10];
            const float pz = R6 * x + R7 * y + R8 * z + sRt[11];
            const float pn = px * px + py * py + pz * pz;
            const float dist = sqrtf(fmaxf(pn + s, 0.0f));

            v[0] = px; v[1] = py; v[2] = pz;
            v[3] = q.x; v[4] = q.y; v[5] = q.z;
            v[6] = px * q.x; v[7] = px * q.y; v[8] = px * q.z;
            v[9] = py * q.x; v[10] = py * q.y; v[11] = py * q.z;
            v[12] = pz * q.x; v[13] = pz * q.y; v[14] = pz * q.z;
            v[15] = dist;
        }

        // fixed-order deterministic block reduction (4 warps)
#pragma unroll
        for (int k = 0; k < 16; k++) {
            float a = v[k];
            a += __shfl_down_sync(0xffffffffu, a, 16);
            a += __shfl_down_sync(0xffffffffu, a, 8);
            a += __shfl_down_sync(0xffffffffu, a, 4);
            a += __shfl_down_sync(0xffffffffu, a, 2);
            a += __shfl_down_sync(0xffffffffu, a, 1);
            v[k] = a;
        }
        const int lane = tid & 31, warp = tid >> 5;
        if (lane == 0) {
#pragma unroll
            for (int k = 0; k < 16; k++) sm[warp][k] = v[k];
        }
        __syncthreads();
        if (tid < 16) {
            float a = sm[0][tid] + sm[1][tid] + sm[2][tid] + sm[3][tid];
            __stcg(&g_part[step][chunk_id][tid], a);
        }
        __syncthreads();
        if (tid == 0) arrive(&g_tailcnt[step * 32]);
        return;
    }

    // =================== final block (one per step) ===================
    {
        __shared__ float cRt[BATCH][12];
        __shared__ float c_S[BATCH][16];
        __shared__ float c_errnew[BATCH];
        __shared__ int c_done, c_done0;

        if (tid == 0) { wait_ge(&g_tailcnt[step * 32], NCNT); c_done0 = __ldcg(&g_done); }
        __syncthreads();
        const int done0 = c_done0;

        if (tid < 24) {
            int bb = tid / 12, j = tid - bb * 12;
            cRt[bb][j] = (j < 9) ? __ldcg(&g_Rcum[bb][j]) : __ldcg(&g_tcum[bb][j - 9]);
        }
        __syncthreads();

        if (tid < 32) {
            const int bsel = tid >> 4, k = tid & 15;
            float a = 0.f;
#pragma unroll
            for (int c = 0; c < NCHB; c++)             // fixed order: deterministic
                a += __ldcg(&g_part[step][bsel * NCHB + c][k]);
            c_S[bsel][k] = a;
            if (k == 15) c_errnew[bsel] = a / (float)NPTS;
        }
        __syncthreads();

        if (tid == 0) {
            int conv = (fabsf(c_errnew[0] - __ldcg(&g_err[0])) < TOLER) &&
                       (fabsf(c_errnew[1] - __ldcg(&g_err[1])) < TOLER);
            c_done = (done0 || conv) ? 1 : 0;
            __stcg(&g_done, c_done);
        }
        __syncthreads();

        if (tid < BATCH && !c_done) {
            float S[16];
#pragma unroll
            for (int k = 0; k < 16; k++) S[k] = c_S[tid][k];
            float Rn[9], tn[3];
            solve_horn_f(S, Rn, tn);

            float Ro[9], to[3];
#pragma unroll
            for (int i = 0; i < 9; i++) Ro[i] = cRt[tid][i];
#pragma unroll
            for (int i = 0; i < 3; i++) to[i] = cRt[tid][9 + i];

#pragma unroll
            for (int i = 0; i < 3; i++) {
#pragma unroll
                for (int j = 0; j < 3; j++) {
                    float m = Rn[i * 3 + 0] * Ro[0 + j] + Rn[i * 3 + 1] * Ro[3 + j] +
                              Rn[i * 3 + 2] * Ro[6 + j];
                    __stcg(&g_Rcum[tid][i * 3 + j], m);
                }
                float tm = Rn[i * 3 + 0] * to[0] + Rn[i * 3 + 1] * to[1] +
                           Rn[i * 3 + 2] * to[2] + tn[i];
                __stcg(&g_tcum[tid][i], tm);
            }
            __stcg(&g_err[tid], c_errnew[tid]);
        }
        __syncthreads();

        if (step == NSTEPS - 1) {
            if (tid < BATCH) {
                float R[9];
#pragma unroll
                for (int i = 0; i < 9; i++) R[i] = __ldcg(&g_Rcum[tid][i]);
                out[tid * 7 + 0] = __ldcg(&g_tcum[tid][0]);
                out[tid * 7 + 1] = __ldcg(&g_tcum[tid][1]);
                out[tid * 7 + 2] = __ldcg(&g_tcum[tid][2]);
                const float r00 = R[0], r11 = R[4], r22 = R[8];
                float qw = 0.5f * sqrtf(fmaxf(1.f + r00 + r11 + r22, 1e-12f));
                float qx = 0.5f * sqrtf(fmaxf(1.f + r00 - r11 - r22, 1e-12f));
                float qy = 0.5f * sqrtf(fmaxf(1.f - r00 + r11 - r22, 1e-12f));
                float qz = 0.5f * sqrtf(fmaxf(1.f - r00 - r11 + r22, 1e-12f));
                qx = (R[7] - R[5] >= 0.f) ? qx : -qx;
                qy = (R[2] - R[6] >= 0.f) ? qy : -qy;
                qz = (R[3] - R[1] >= 0.f) ? qz : -qz;
                out[tid * 7 + 3] = qx;
                out[tid * 7 + 4] = qy;
                out[tid * 7 + 5] = qz;
                out[tid * 7 + 6] = qw;
            }
        } else {
            if (tid == 0) release_phase(&g_phase, (unsigned)(step + 1));
        }
    }
}

// ---------------- launch ----------------
extern "C" void kernel_launch(void* const* d_in, const int* in_sizes, int n_in,
                              void* d_out, int out_size) {
    const float* psrc = (const float*)d_in[0];
    const float* ptgt = (const float*)d_in[1];
    float* out = (float*)d_out;

    init_kernel<<<(BATCH * MPTS + 255) / 256, 256>>>(ptgt);
    icp_all_kernel<<<TOTAL_BLKS, TPB>>>(psrc, out);
}